// round 9
// baseline (speedup 1.0000x reference)
#include <cuda_runtime.h>

// Capsule dynamic routing. B=64, N=4096, I=8, C=32, D=16, 3 routing iters.
// prep_W: coalesced interleave of W into g_Wil[n][r][c] f4 (r=jp*4+i2).
// caps_pass0: 512 thr, 16 warps = 8 groups x 2 j-halves; group owns 8 b;
//   direct accumulate (uniform coupling); i2-streamed W rows (low regs).
// caps_pass12: 512 thr, 16 warps = 8 pairs x 2 j-halves; pair owns 4 b;
//   o j-half hoisted to regs; hat via i2-streamed rows; partial logits
//   exchanged through smem + named 64-thread barrier (2-slot rotation);
//   softmax = warp shfl over c (lane=c); all math fma.rn.f32x2.
// caps_reduce: 256 CTAs, 8-way chunk split + shfl merge + squash.

#define B_ 64
#define N_ 4096
#define C_ 32

using u64 = unsigned long long;

__device__ float4 g_Wil[(size_t)N_ * 1024];              // 64MB interleaved W
__device__ float g_part[(size_t)128 * B_ * C_ * 16];     // 16MB partials
__device__ float g_Ocum[B_ * C_ * 16];                   // cumulative outs

__device__ __forceinline__ u64 fma2(u64 a, u64 b, u64 c) {
    u64 d; asm("fma.rn.f32x2 %0,%1,%2,%3;" : "=l"(d) : "l"(a), "l"(b), "l"(c)); return d;
}
__device__ __forceinline__ u64 mul2(u64 a, u64 b) {
    u64 d; asm("mul.rn.f32x2 %0,%1,%2;" : "=l"(d) : "l"(a), "l"(b)); return d;
}
__device__ __forceinline__ u64 pack2(float x) {
    u64 d; asm("mov.b64 %0,{%1,%1};" : "=l"(d) : "f"(x)); return d;
}
__device__ __forceinline__ float hadd2(u64 v) {
    float a, b; asm("mov.b64 {%0,%1},%2;" : "=f"(a), "=f"(b) : "l"(v)); return a + b;
}
__device__ __forceinline__ float2 unpk(u64 v) {
    float a, b; asm("mov.b64 {%0,%1},%2;" : "=f"(a), "=f"(b) : "l"(v)); return make_float2(a, b);
}
__device__ __forceinline__ unsigned smem_u32(const void* p) {
    unsigned a; asm("{ .reg .u64 t; cvta.to.shared.u64 t, %1; cvt.u32.u64 %0, t; }" : "=r"(a) : "l"(p));
    return a;
}
__device__ __forceinline__ void cpa16(unsigned dst, const void* src) {
    asm volatile("cp.async.cg.shared.global [%0], [%1], 16;" :: "r"(dst), "l"(src));
}
__device__ __forceinline__ void cpa_commit() { asm volatile("cp.async.commit_group;"); }
__device__ __forceinline__ void cpa_wait1() { asm volatile("cp.async.wait_group 1;"); }
__device__ __forceinline__ void cpa_wait0() { asm volatile("cp.async.wait_group 0;"); }

// ---------------- prep_W: coalesced interleave via smem tile (unchanged) ----------------
__global__ void __launch_bounds__(256, 1)
prep_W(const float* __restrict__ W) {
    extern __shared__ float4 sR[];                      // [c][257]
    const int nb0 = blockIdx.x * 8;
    const int tid = threadIdx.x, c = tid & 31, w = tid >> 5;

    const float4* Wf4 = reinterpret_cast<const float4*>(W);
    #pragma unroll
    for (int cc = 0; cc < 32; ++cc)
        sR[cc * 257 + tid] = Wf4[((size_t)cc * N_ + nb0) * 32 + tid];
    __syncthreads();

    #pragma unroll
    for (int it = 0; it < 32; ++it) {
        const int row = it * 8 + w;
        const int nn = row >> 5, r = row & 31;
        const int jp = r >> 2, i2 = r & 3;
        const int ih = i2 >> 1, part = i2 & 1;
        float4 A = sR[c * 257 + nn * 32 + 4 * jp + ih];
        float4 Bv = sR[c * 257 + nn * 32 + 4 * jp + 2 + ih];
        float4 o = part == 0 ? make_float4(A.x, Bv.x, A.y, Bv.y)
                             : make_float4(A.z, Bv.z, A.w, Bv.w);
        g_Wil[(size_t)(nb0 + nn) * 1024 + r * 32 + c] = o;
    }
}

// ---------------- pass 0: uniform coupling, 512 thr, j-half groups ----------------
// grid 128 (32 n each). 16 warps = (pr in 8) x (jh in 2); pr owns b = pr*8+bi.
// smem: sW 64KB (2 buf x 2 n) + sX 128KB (64 b x 32 n dup pairs).
__global__ void __launch_bounds__(512, 1)
caps_pass0(const float* __restrict__ X) {
    extern __shared__ char smraw[];
    float4* sW = reinterpret_cast<float4*>(smraw);               // 4096 f4
    u64* sX = reinterpret_cast<u64*>(smraw + 65536);             // 16384 u64
    const int chunk = blockIdx.x, n0 = chunk * 32;
    const int tid = threadIdx.x, c = tid & 31, w = tid >> 5;
    const int pr = w >> 1, jh = w & 1;
    const unsigned sWa = smem_u32(sW);

    // stage X dup pairs: sX[bl 64][nloc 32][i 8]
    for (int t = tid; t < 64 * 32 * 2; t += 512) {
        int bl = t >> 6, rem = t & 63;
        float4 v = reinterpret_cast<const float4*>(X)[(size_t)bl * 8192 + n0 * 2 + rem];
        u64* d = sX + bl * 256 + (rem >> 1) * 8 + (rem & 1) * 4;
        d[0] = pack2(v.x); d[1] = pack2(v.y); d[2] = pack2(v.z); d[3] = pack2(v.w);
    }

    u64 acc[8][4];                                      // [bi][jpl], j-half
    #pragma unroll
    for (int bi = 0; bi < 8; ++bi)
        #pragma unroll
        for (int j = 0; j < 4; ++j) acc[bi][j] = 0ull;

    auto stage = [&](int sub, int buf) {                // 2 n = 2048 f4 = 32KB
        const float4* src = g_Wil + (size_t)(n0 + sub * 2) * 1024;
        unsigned dst = sWa + (unsigned)(buf * 2048 + tid) * 16;
        #pragma unroll
        for (int k = 0; k < 4; ++k) cpa16(dst + k * 8192, src + tid + k * 512);
        cpa_commit();
    };
    stage(0, 0);

    const ulonglong2* X2 = reinterpret_cast<const ulonglong2*>(sX);
    for (int sub = 0; sub < 16; ++sub) {
        if (sub < 15) { stage(sub + 1, (sub + 1) & 1); cpa_wait1(); }
        else cpa_wait0();
        __syncthreads();
        const float4* Wb = sW + (sub & 1) * 2048;
        #pragma unroll
        for (int ln = 0; ln < 2; ++ln) {
            const ulonglong2* W2 = reinterpret_cast<const ulonglong2*>(Wb + ln * 1024);
            const int nloc = sub * 2 + ln;
            #pragma unroll
            for (int i2 = 0; i2 < 4; ++i2) {
                ulonglong2 Wr[4];
                #pragma unroll
                for (int jpl = 0; jpl < 4; ++jpl)
                    Wr[jpl] = W2[(jh * 16 + jpl * 4 + i2) * 32 + c];
                #pragma unroll
                for (int bi = 0; bi < 8; ++bi) {
                    ulonglong2 xv = X2[(pr * 8 + bi) * 128 + nloc * 4 + i2];
                    #pragma unroll
                    for (int jpl = 0; jpl < 4; ++jpl) {
                        u64 t = fma2(xv.x, Wr[jpl].x, acc[bi][jpl]);
                        acc[bi][jpl] = fma2(xv.y, Wr[jpl].y, t);
                    }
                }
            }
        }
        __syncthreads();
    }

    #pragma unroll
    for (int bi = 0; bi < 8; ++bi) {
        const int b = pr * 8 + bi;
        float4* dst = reinterpret_cast<float4*>(g_part)
                        + (((size_t)chunk * B_ + b) * C_ + c) * 4 + jh * 2;
        float2 p0 = unpk(acc[bi][0]), p1 = unpk(acc[bi][1]);
        float2 p2 = unpk(acc[bi][2]), p3 = unpk(acc[bi][3]);
        dst[0] = make_float4(p0.x * (1.f / 32.f), p0.y * (1.f / 32.f),
                             p1.x * (1.f / 32.f), p1.y * (1.f / 32.f));
        dst[1] = make_float4(p2.x * (1.f / 32.f), p2.y * (1.f / 32.f),
                             p3.x * (1.f / 32.f), p3.y * (1.f / 32.f));
    }
}

// ---------------- pass 1/2: 512 thr, j-half warp pairs ----------------
// grid (64 n-chunks, 2 b-halves) = 128. 16 warps = (pr in 8) x (jh in 2);
// pr owns b = b0 + pr*4 + bi. smem: sW 64KB + sX 128KB + sLog 16KB = 208KB.
// sLog layout: [pr 8][slot 2][jh 2][c 32] float4 (plog for 4 bi).
__global__ void __launch_bounds__(512, 1)
caps_pass12(const float* __restrict__ X) {
    extern __shared__ char smraw[];
    float4* sW = reinterpret_cast<float4*>(smraw);                  // 4096 f4
    u64* sX = reinterpret_cast<u64*>(smraw + 65536);                // 16384 u64
    float4* sLog = reinterpret_cast<float4*>(smraw + 196608);       // 1024 f4
    const int chunk = blockIdx.x, half = blockIdx.y;
    const int n0 = chunk * 64, b0 = half * 32;
    const int tid = threadIdx.x, c = tid & 31, w = tid >> 5;
    const int pr = w >> 1, jh = w & 1;
    const unsigned sWa = smem_u32(sW);

    // stage X dup pairs: sX[bl 32][nloc 64][i 8]
    for (int t = tid; t < 32 * 64 * 2; t += 512) {
        int bl = t >> 7, rem = t & 127;
        float4 v = reinterpret_cast<const float4*>(X)[(size_t)(b0 + bl) * 8192 + n0 * 2 + rem];
        u64* d = sX + bl * 512 + (rem >> 1) * 8 + (rem & 1) * 4;
        d[0] = pack2(v.x); d[1] = pack2(v.y); d[2] = pack2(v.z); d[3] = pack2(v.w);
    }

    // hoist my j-half of o: o2h[bi][jpl] = (o_{2j}, o_{2j+1}), jp = jh*4+jpl
    u64 o2h[4][4];
    #pragma unroll
    for (int bi = 0; bi < 4; ++bi) {
        const int b = b0 + pr * 4 + bi;
        const ulonglong2* op = reinterpret_cast<const ulonglong2*>(
            g_Ocum + ((size_t)b * C_ + c) * 16 + jh * 8);
        ulonglong2 u0 = op[0], u1 = op[1];
        o2h[bi][0] = u0.x; o2h[bi][1] = u0.y; o2h[bi][2] = u1.x; o2h[bi][3] = u1.y;
    }

    u64 acc[4][4];
    #pragma unroll
    for (int bi = 0; bi < 4; ++bi)
        #pragma unroll
        for (int j = 0; j < 4; ++j) acc[bi][j] = 0ull;

    auto stage = [&](int sub, int buf) {
        const float4* src = g_Wil + (size_t)(n0 + sub * 2) * 1024;
        unsigned dst = sWa + (unsigned)(buf * 2048 + tid) * 16;
        #pragma unroll
        for (int k = 0; k < 4; ++k) cpa16(dst + k * 8192, src + tid + k * 512);
        cpa_commit();
    };
    stage(0, 0);

    const ulonglong2* X2 = reinterpret_cast<const ulonglong2*>(sX);
    for (int sub = 0; sub < 32; ++sub) {
        if (sub < 31) { stage(sub + 1, (sub + 1) & 1); cpa_wait1(); }
        else cpa_wait0();
        __syncthreads();
        const float4* Wb = sW + (sub & 1) * 2048;
        #pragma unroll
        for (int ln = 0; ln < 2; ++ln) {
            const ulonglong2* W2 = reinterpret_cast<const ulonglong2*>(Wb + ln * 1024);
            const int nloc = sub * 2 + ln;
            u64 hat[4][4];
            #pragma unroll
            for (int i2 = 0; i2 < 4; ++i2) {
                ulonglong2 Wr[4];
                #pragma unroll
                for (int jpl = 0; jpl < 4; ++jpl)
                    Wr[jpl] = W2[(jh * 16 + jpl * 4 + i2) * 32 + c];
                #pragma unroll
                for (int bi = 0; bi < 4; ++bi) {
                    ulonglong2 xv = X2[(pr * 4 + bi) * 256 + nloc * 4 + i2];
                    #pragma unroll
                    for (int jpl = 0; jpl < 4; ++jpl) {
                        u64 t = (i2 == 0) ? mul2(xv.x, Wr[jpl].x)
                                          : fma2(xv.x, Wr[jpl].x, hat[bi][jpl]);
                        hat[bi][jpl] = fma2(xv.y, Wr[jpl].y, t);
                    }
                }
            }
            // partial logits over my j-half
            float plog[4];
            #pragma unroll
            for (int bi = 0; bi < 4; ++bi) {
                u64 lg = mul2(hat[bi][0], o2h[bi][0]);
                lg = fma2(hat[bi][1], o2h[bi][1], lg);
                lg = fma2(hat[bi][2], o2h[bi][2], lg);
                lg = fma2(hat[bi][3], o2h[bi][3], lg);
                plog[bi] = hadd2(lg);
            }
            // exchange with partner warp (2-slot rotation, named 64-thr barrier)
            const int slot = nloc & 1;
            sLog[((pr * 2 + slot) * 2 + jh) * 32 + c] =
                make_float4(plog[0], plog[1], plog[2], plog[3]);
            asm volatile("bar.sync %0, 64;" :: "r"(pr + 1) : "memory");
            float4 other = sLog[((pr * 2 + slot) * 2 + (1 - jh)) * 32 + c];
            const float lgt[4] = {plog[0] + other.x, plog[1] + other.y,
                                  plog[2] + other.z, plog[3] + other.w};
            #pragma unroll
            for (int bi = 0; bi < 4; ++bi) {
                const float e = __expf(lgt[bi]);   // logits O(1): no max-sub needed
                float s = e;
                s += __shfl_xor_sync(0xffffffffu, s, 1);
                s += __shfl_xor_sync(0xffffffffu, s, 2);
                s += __shfl_xor_sync(0xffffffffu, s, 4);
                s += __shfl_xor_sync(0xffffffffu, s, 8);
                s += __shfl_xor_sync(0xffffffffu, s, 16);
                const u64 cf = pack2(__fdividef(e, s));
                #pragma unroll
                for (int jpl = 0; jpl < 4; ++jpl)
                    acc[bi][jpl] = fma2(cf, hat[bi][jpl], acc[bi][jpl]);
            }
        }
        __syncthreads();
    }

    // flush my j-half of partials
    #pragma unroll
    for (int bi = 0; bi < 4; ++bi) {
        const int b = b0 + pr * 4 + bi;
        float4* dst = reinterpret_cast<float4*>(g_part)
                        + (((size_t)chunk * B_ + b) * C_ + c) * 4 + jh * 2;
        float2 p0 = unpk(acc[bi][0]), p1 = unpk(acc[bi][1]);
        float2 p2 = unpk(acc[bi][2]), p3 = unpk(acc[bi][3]);
        dst[0] = make_float4(p0.x, p0.y, p1.x, p1.y);
        dst[1] = make_float4(p2.x, p2.y, p3.x, p3.y);
    }
}

// ---------------- reduce + squash: grid 256 x 256, 8-way chunk split ----------------
__global__ void caps_reduce(float* __restrict__ out, int mode, int nch) {
    const int gt = blockIdx.x * 256 + threadIdx.x;
    const int idx4 = gt >> 3, eighth = gt & 7;
    const int kc = nch >> 3;
    float4 a = make_float4(0.f, 0.f, 0.f, 0.f);
    const float4* gp = reinterpret_cast<const float4*>(g_part) + idx4;
    #pragma unroll 8
    for (int k = 0; k < kc; ++k) {
        float4 v = gp[(size_t)(eighth * kc + k) * 8192];
        a.x += v.x; a.y += v.y; a.z += v.z; a.w += v.w;
    }
    #pragma unroll
    for (int m = 1; m <= 4; m <<= 1) {
        a.x += __shfl_xor_sync(0xffffffffu, a.x, m);
        a.y += __shfl_xor_sync(0xffffffffu, a.y, m);
        a.z += __shfl_xor_sync(0xffffffffu, a.z, m);
        a.w += __shfl_xor_sync(0xffffffffu, a.w, m);
    }
    float sq = a.x * a.x + a.y * a.y + a.z * a.z + a.w * a.w;
    sq += __shfl_xor_sync(0xffffffffu, sq, 8);
    sq += __shfl_xor_sync(0xffffffffu, sq, 16);
    const float f = sq / ((1.f + sq) * sqrtf(sq + 1e-7f));
    float4 v = make_float4(a.x * f, a.y * f, a.z * f, a.w * f);
    if (eighth == 0) {
        float4* oc = reinterpret_cast<float4*>(g_Ocum);
        if (mode == 0) {
            oc[idx4] = v;
        } else if (mode == 1) {
            float4 o = oc[idx4];
            o.x += v.x; o.y += v.y; o.z += v.z; o.w += v.w;
            oc[idx4] = o;
        } else {
            reinterpret_cast<float4*>(out)[idx4] = v;
        }
    }
}

extern "C" void kernel_launch(void* const* d_in, const int* in_sizes, int n_in,
                              void* d_out, int out_size) {
    const float* X = (const float*)d_in[0];
    const float* W = (const float*)d_in[1];
    if (n_in >= 2 && in_sizes[0] != B_ * N_ * 8) {
        X = (const float*)d_in[1];
        W = (const float*)d_in[0];
    }
    float* out = (float*)d_out;

    const int smemP  = 32 * 257 * 16;                // 131584 B
    const int smem0  = 65536 + 131072;               // 196608 B
    const int smem12 = 65536 + 131072 + 16384;       // 212992 B
    cudaFuncSetAttribute(prep_W,      cudaFuncAttributeMaxDynamicSharedMemorySize, smemP);
    cudaFuncSetAttribute(caps_pass0,  cudaFuncAttributeMaxDynamicSharedMemorySize, smem0);
    cudaFuncSetAttribute(caps_pass12, cudaFuncAttributeMaxDynamicSharedMemorySize, smem12);

    prep_W<<<512, 256, smemP>>>(W);
    caps_pass0<<<128, 512, smem0>>>(X);
    caps_reduce<<<256, 256>>>(out, 0, 128);
    caps_pass12<<<dim3(64, 2), 512, smem12>>>(X);
    caps_reduce<<<256, 256>>>(out, 1, 64);
    caps_pass12<<<dim3(64, 2), 512, smem12>>>(X);
    caps_reduce<<<256, 256>>>(out, 2, 64);
}

// round 11
// speedup vs baseline: 1.1390x; 1.1390x over previous
#include <cuda_runtime.h>

// Capsule dynamic routing. B=64, N=4096, I=8, C=32, D=16, 3 routing iters.
// prep_W: one-time interleave of W into g_Wil[n][r][c] (r=jp*4+i2; f4 = j-pair
//   values for i=2i2,2i2+1) enabling linear cp.async staging.
// caps_pass0: uniform coupling; 8 b/thread, all 64 b per CTA, 32 n/CTA, grid 128.
// caps_pass12: 4 b/thread, 32 b + 64 n per CTA, grid (64,2); o hoisted to regs;
//   hat/logit/acc in fma.rn.f32x2; softmax = 5-shfl butterfly (lane = c).
// caps_reduce: 256 CTAs, 8-way chunk split + shfl merge + squash.

#define B_ 64
#define N_ 4096
#define C_ 32

using u64 = unsigned long long;

__device__ float4 g_Wil[(size_t)N_ * 1024];              // 64MB interleaved W
__device__ float g_part[(size_t)128 * B_ * C_ * 16];     // 16MB partials
__device__ float g_Ocum[B_ * C_ * 16];                   // cumulative outs

__device__ __forceinline__ u64 fma2(u64 a, u64 b, u64 c) {
    u64 d; asm("fma.rn.f32x2 %0,%1,%2,%3;" : "=l"(d) : "l"(a), "l"(b), "l"(c)); return d;
}
__device__ __forceinline__ u64 mul2(u64 a, u64 b) {
    u64 d; asm("mul.rn.f32x2 %0,%1,%2;" : "=l"(d) : "l"(a), "l"(b)); return d;
}
__device__ __forceinline__ u64 pack2(float x) {
    u64 d; asm("mov.b64 %0,{%1,%1};" : "=l"(d) : "f"(x)); return d;
}
__device__ __forceinline__ float hadd2(u64 v) {
    float a, b; asm("mov.b64 {%0,%1},%2;" : "=f"(a), "=f"(b) : "l"(v)); return a + b;
}
__device__ __forceinline__ float2 unpk(u64 v) {
    float a, b; asm("mov.b64 {%0,%1},%2;" : "=f"(a), "=f"(b) : "l"(v)); return make_float2(a, b);
}
__device__ __forceinline__ unsigned smem_u32(const void* p) {
    unsigned a; asm("{ .reg .u64 t; cvta.to.shared.u64 t, %1; cvt.u32.u64 %0, t; }" : "=r"(a) : "l"(p));
    return a;
}
__device__ __forceinline__ void cpa16(unsigned dst, const void* src) {
    asm volatile("cp.async.cg.shared.global [%0], [%1], 16;" :: "r"(dst), "l"(src));
}
__device__ __forceinline__ void cpa_commit() { asm volatile("cp.async.commit_group;"); }
__device__ __forceinline__ void cpa_wait1() { asm volatile("cp.async.wait_group 1;"); }
__device__ __forceinline__ void cpa_wait0() { asm volatile("cp.async.wait_group 0;"); }

// ---------------- W interleave prepass: grid 4096 x 256 ----------------
__global__ void prep_W(const float* __restrict__ W) {
    const int tid = threadIdx.x;
    const int c = tid & 31, jp = tid >> 5;          // jp 0..7
    const int n = blockIdx.x;
    const float4* gp = reinterpret_cast<const float4*>(W)
                         + (((size_t)c * N_ + n) * 16 + 2 * jp) * 2;
    float4 A0 = gp[0], A1 = gp[1], B0 = gp[2], B1 = gp[3];  // rows j=2jp, 2jp+1
    float4* dst = g_Wil + (size_t)n * 1024 + (jp * 4) * 32 + c;
    dst[0]  = make_float4(A0.x, B0.x, A0.y, B0.y);   // i2=0
    dst[32] = make_float4(A0.z, B0.z, A0.w, B0.w);   // i2=1
    dst[64] = make_float4(A1.x, B1.x, A1.y, B1.y);   // i2=2
    dst[96] = make_float4(A1.z, B1.z, A1.w, B1.w);   // i2=3
}

// ---------------- pass 0: uniform coupling, 8 b/thread ----------------
// grid 128 (chunks of 32 n), 256 thr. smem: sW 64KB (2 buf x 2 n) + sXp 128KB.
__global__ void __launch_bounds__(256, 1)
caps_pass0(const float* __restrict__ X) {
    extern __shared__ char smraw[];
    float4* sW = reinterpret_cast<float4*>(smraw);               // 4096 f4
    u64* sXp = reinterpret_cast<u64*>(smraw + 65536);            // [bl][n][i] dup pairs
    const int chunk = blockIdx.x, n0 = chunk * 32;
    const int tid = threadIdx.x, c = tid & 31, w = tid >> 5;
    const unsigned sWa = smem_u32(sW);

    // stage X as duplicated pairs
    for (int t = tid; t < 64 * 32 * 2; t += 256) {
        int bl = t >> 6, rem = t & 63;                           // rem = n*2+ih
        float4 v = reinterpret_cast<const float4*>(X)[(size_t)bl * 8192 + n0 * 2 + rem];
        u64* d = sXp + bl * 256 + (rem >> 1) * 8 + (rem & 1) * 4;
        d[0] = pack2(v.x); d[1] = pack2(v.y); d[2] = pack2(v.z); d[3] = pack2(v.w);
    }

    u64 acc[8][8];
    #pragma unroll
    for (int bi = 0; bi < 8; ++bi)
        #pragma unroll
        for (int q = 0; q < 8; ++q) acc[bi][q] = 0ull;

    // double-buffered W staging: 2 n (2048 f4 = 32KB) per sub
    auto stage = [&](int sub, int buf) {
        const float4* src = g_Wil + (size_t)(n0 + sub * 2) * 1024;
        unsigned dst = sWa + (unsigned)(buf * 2048 + tid) * 16;
        #pragma unroll
        for (int k = 0; k < 8; ++k) cpa16(dst + k * 4096, src + tid + k * 256);
        cpa_commit();
    };
    stage(0, 0);

    for (int sub = 0; sub < 16; ++sub) {
        if (sub < 15) { stage(sub + 1, (sub + 1) & 1); cpa_wait1(); }
        else cpa_wait0();
        __syncthreads();
        const float4* Wb = sW + (sub & 1) * 2048;
        #pragma unroll
        for (int ln = 0; ln < 2; ++ln) {
            const float4* Wn = Wb + ln * 1024;
            const int nloc = sub * 2 + ln;
            #pragma unroll
            for (int q = 0; q < 4; ++q) {
                ulonglong2 Wq[8];
                #pragma unroll
                for (int k = 0; k < 8; ++k)
                    Wq[k] = reinterpret_cast<const ulonglong2*>(Wn + (q * 8 + k) * 32)[c];
                #pragma unroll
                for (int bi = 0; bi < 8; ++bi) {
                    const ulonglong2* xp = reinterpret_cast<const ulonglong2*>(
                        sXp + (w * 8 + bi) * 256 + nloc * 8);
                    ulonglong2 xA = xp[0], xB = xp[1], xC = xp[2], xD = xp[3];
                    u64 a0 = acc[bi][2 * q], a1 = acc[bi][2 * q + 1];
                    a0 = fma2(xA.x, Wq[0].x, a0); a0 = fma2(xA.y, Wq[0].y, a0);
                    a0 = fma2(xB.x, Wq[1].x, a0); a0 = fma2(xB.y, Wq[1].y, a0);
                    a0 = fma2(xC.x, Wq[2].x, a0); a0 = fma2(xC.y, Wq[2].y, a0);
                    a0 = fma2(xD.x, Wq[3].x, a0); a0 = fma2(xD.y, Wq[3].y, a0);
                    a1 = fma2(xA.x, Wq[4].x, a1); a1 = fma2(xA.y, Wq[4].y, a1);
                    a1 = fma2(xB.x, Wq[5].x, a1); a1 = fma2(xB.y, Wq[5].y, a1);
                    a1 = fma2(xC.x, Wq[6].x, a1); a1 = fma2(xC.y, Wq[6].y, a1);
                    a1 = fma2(xD.x, Wq[7].x, a1); a1 = fma2(xD.y, Wq[7].y, a1);
                    acc[bi][2 * q] = a0; acc[bi][2 * q + 1] = a1;
                }
            }
        }
        __syncthreads();
    }

    #pragma unroll
    for (int bi = 0; bi < 8; ++bi) {
        const int b = w * 8 + bi;
        float4* dst = reinterpret_cast<float4*>(g_part) + (((size_t)chunk * B_ + b) * C_ + c) * 4;
        #pragma unroll
        for (int qd = 0; qd < 4; ++qd) {
            float2 p0 = unpk(acc[bi][2 * qd]), p1 = unpk(acc[bi][2 * qd + 1]);
            dst[qd] = make_float4(p0.x * (1.f / 32.f), p0.y * (1.f / 32.f),
                                  p1.x * (1.f / 32.f), p1.y * (1.f / 32.f));
        }
    }
}

// ---------------- pass 1/2: routed coupling, 4 b/thread, o in regs ----------------
// grid (64 chunks, 2 b-halves), 256 thr. smem: sW 64KB + sXp 128KB.
__global__ void __launch_bounds__(256, 1)
caps_pass12(const float* __restrict__ X) {
    extern __shared__ char smraw[];
    float4* sW = reinterpret_cast<float4*>(smraw);
    u64* sXp = reinterpret_cast<u64*>(smraw + 65536);            // [bl 32][n 64][i 8]
    const int chunk = blockIdx.x, half = blockIdx.y;
    const int n0 = chunk * 64, b0 = half * 32;
    const int tid = threadIdx.x, c = tid & 31, w = tid >> 5;
    const unsigned sWa = smem_u32(sW);

    for (int t = tid; t < 32 * 64 * 2; t += 256) {
        int bl = t >> 7, rem = t & 127;
        float4 v = reinterpret_cast<const float4*>(X)[(size_t)(b0 + bl) * 8192 + n0 * 2 + rem];
        u64* d = sXp + bl * 512 + (rem >> 1) * 8 + (rem & 1) * 4;
        d[0] = pack2(v.x); d[1] = pack2(v.y); d[2] = pack2(v.z); d[3] = pack2(v.w);
    }

    // hoist o (cumulative outs) to registers: loop-invariant over n
    u64 o2[4][8];
    #pragma unroll
    for (int bi = 0; bi < 4; ++bi) {
        const int b = b0 + w * 4 + bi;
        const ulonglong2* op = reinterpret_cast<const ulonglong2*>(g_Ocum + (b * C_ + c) * 16);
        #pragma unroll
        for (int qd = 0; qd < 4; ++qd) {
            ulonglong2 u = op[qd];
            o2[bi][2 * qd] = u.x; o2[bi][2 * qd + 1] = u.y;
        }
    }

    u64 acc[4][8];
    #pragma unroll
    for (int bi = 0; bi < 4; ++bi)
        #pragma unroll
        for (int jp = 0; jp < 8; ++jp) acc[bi][jp] = 0ull;

    auto stage = [&](int sub, int buf) {
        const float4* src = g_Wil + (size_t)(n0 + sub * 2) * 1024;
        unsigned dst = sWa + (unsigned)(buf * 2048 + tid) * 16;
        #pragma unroll
        for (int k = 0; k < 8; ++k) cpa16(dst + k * 4096, src + tid + k * 256);
        cpa_commit();
    };
    stage(0, 0);

    for (int sub = 0; sub < 32; ++sub) {
        if (sub < 31) { stage(sub + 1, (sub + 1) & 1); cpa_wait1(); }
        else cpa_wait0();
        __syncthreads();
        const float4* Wb = sW + (sub & 1) * 2048;
        #pragma unroll
        for (int ln = 0; ln < 2; ++ln) {
            const float4* Wn = Wb + ln * 1024;
            const int nloc = sub * 2 + ln;
            u64 hat[4][8];
            #pragma unroll
            for (int q = 0; q < 4; ++q) {
                ulonglong2 Wq[8];
                #pragma unroll
                for (int k = 0; k < 8; ++k)
                    Wq[k] = reinterpret_cast<const ulonglong2*>(Wn + (q * 8 + k) * 32)[c];
                #pragma unroll
                for (int bi = 0; bi < 4; ++bi) {
                    const ulonglong2* xp = reinterpret_cast<const ulonglong2*>(
                        sXp + (w * 4 + bi) * 512 + nloc * 8);
                    ulonglong2 xA = xp[0], xB = xp[1], xC = xp[2], xD = xp[3];
                    u64 h0 = mul2(xA.x, Wq[0].x);
                    h0 = fma2(xA.y, Wq[0].y, h0);
                    h0 = fma2(xB.x, Wq[1].x, h0); h0 = fma2(xB.y, Wq[1].y, h0);
                    h0 = fma2(xC.x, Wq[2].x, h0); h0 = fma2(xC.y, Wq[2].y, h0);
                    h0 = fma2(xD.x, Wq[3].x, h0); h0 = fma2(xD.y, Wq[3].y, h0);
                    u64 h1 = mul2(xA.x, Wq[4].x);
                    h1 = fma2(xA.y, Wq[4].y, h1);
                    h1 = fma2(xB.x, Wq[5].x, h1); h1 = fma2(xB.y, Wq[5].y, h1);
                    h1 = fma2(xC.x, Wq[6].x, h1); h1 = fma2(xC.y, Wq[6].y, h1);
                    h1 = fma2(xD.x, Wq[7].x, h1); h1 = fma2(xD.y, Wq[7].y, h1);
                    hat[bi][2 * q] = h0; hat[bi][2 * q + 1] = h1;
                }
            }
            #pragma unroll
            for (int bi = 0; bi < 4; ++bi) {
                u64 lg = mul2(hat[bi][0], o2[bi][0]);
                lg = fma2(hat[bi][1], o2[bi][1], lg);
                lg = fma2(hat[bi][2], o2[bi][2], lg); lg = fma2(hat[bi][3], o2[bi][3], lg);
                lg = fma2(hat[bi][4], o2[bi][4], lg); lg = fma2(hat[bi][5], o2[bi][5], lg);
                lg = fma2(hat[bi][6], o2[bi][6], lg); lg = fma2(hat[bi][7], o2[bi][7], lg);
                const float e = __expf(hadd2(lg));   // logits O(1): no max-sub needed
                float s = e;
                s += __shfl_xor_sync(0xffffffffu, s, 1);
                s += __shfl_xor_sync(0xffffffffu, s, 2);
                s += __shfl_xor_sync(0xffffffffu, s, 4);
                s += __shfl_xor_sync(0xffffffffu, s, 8);
                s += __shfl_xor_sync(0xffffffffu, s, 16);
                const u64 cf = pack2(__fdividef(e, s));
                #pragma unroll
                for (int jp = 0; jp < 8; ++jp)
                    acc[bi][jp] = fma2(cf, hat[bi][jp], acc[bi][jp]);
            }
        }
        __syncthreads();
    }

    #pragma unroll
    for (int bi = 0; bi < 4; ++bi) {
        const int b = b0 + w * 4 + bi;
        float4* dst = reinterpret_cast<float4*>(g_part) + (((size_t)chunk * B_ + b) * C_ + c) * 4;
        #pragma unroll
        for (int qd = 0; qd < 4; ++qd) {
            float2 p0 = unpk(acc[bi][2 * qd]), p1 = unpk(acc[bi][2 * qd + 1]);
            dst[qd] = make_float4(p0.x, p0.y, p1.x, p1.y);
        }
    }
}

// ---------------- reduce + squash: grid 256 x 256, 8-way chunk split ----------------
__global__ void caps_reduce(float* __restrict__ out, int mode, int nch) {
    const int gt = blockIdx.x * 256 + threadIdx.x;    // 0..65535
    const int idx4 = gt >> 3, eighth = gt & 7;        // idx4 0..8191
    const int kc = nch >> 3;
    float4 a = make_float4(0.f, 0.f, 0.f, 0.f);
    const float4* gp = reinterpret_cast<const float4*>(g_part) + idx4;
    #pragma unroll 8
    for (int k = 0; k < kc; ++k) {
        float4 v = gp[(size_t)(eighth * kc + k) * 8192];
        a.x += v.x; a.y += v.y; a.z += v.z; a.w += v.w;
    }
    // merge eighths (lanes xor 1,2,4 share idx4)
    #pragma unroll
    for (int m = 1; m <= 4; m <<= 1) {
        a.x += __shfl_xor_sync(0xffffffffu, a.x, m);
        a.y += __shfl_xor_sync(0xffffffffu, a.y, m);
        a.z += __shfl_xor_sync(0xffffffffu, a.z, m);
        a.w += __shfl_xor_sync(0xffffffffu, a.w, m);
    }
    // squash: ||s||^2 over 16 j = 4 idx4 (lanes xor 8,16)
    float sq = a.x * a.x + a.y * a.y + a.z * a.z + a.w * a.w;
    sq += __shfl_xor_sync(0xffffffffu, sq, 8);
    sq += __shfl_xor_sync(0xffffffffu, sq, 16);
    const float f = sq / ((1.f + sq) * sqrtf(sq + 1e-7f));
    float4 v = make_float4(a.x * f, a.y * f, a.z * f, a.w * f);
    if (eighth == 0) {
        float4* oc = reinterpret_cast<float4*>(g_Ocum);
        if (mode == 0) {
            oc[idx4] = v;
        } else if (mode == 1) {
            float4 o = oc[idx4];
            o.x += v.x; o.y += v.y; o.z += v.z; o.w += v.w;
            oc[idx4] = o;
        } else {
            reinterpret_cast<float4*>(out)[idx4] = v;
        }
    }
}

extern "C" void kernel_launch(void* const* d_in, const int* in_sizes, int n_in,
                              void* d_out, int out_size) {
    const float* X = (const float*)d_in[0];
    const float* W = (const float*)d_in[1];
    if (n_in >= 2 && in_sizes[0] != B_ * N_ * 8) {
        X = (const float*)d_in[1];
        W = (const float*)d_in[0];
    }
    float* out = (float*)d_out;

    const int smem0  = 65536 + 131072;   // 192KB
    const int smem12 = 65536 + 131072;   // 192KB
    cudaFuncSetAttribute(caps_pass0,  cudaFuncAttributeMaxDynamicSharedMemorySize, smem0);
    cudaFuncSetAttribute(caps_pass12, cudaFuncAttributeMaxDynamicSharedMemorySize, smem12);

    prep_W<<<N_, 256>>>(W);
    caps_pass0<<<128, 256, smem0>>>(X);
    caps_reduce<<<256, 256>>>(out, 0, 128);
    caps_pass12<<<dim3(64, 2), 256, smem12>>>(X);
    caps_reduce<<<256, 256>>>(out, 1, 64);
    caps_pass12<<<dim3(64, 2), 256, smem12>>>(X);
    caps_reduce<<<256, 256>>>(out, 2, 64);
}